// round 13
// baseline (speedup 1.0000x reference)
#include <cuda_runtime.h>
#include <cuda_fp16.h>
#include <cstdint>

#define T_TOK 2048
#define HID   2048
#define NEXP  64
#define IDIM  768
#define TOPK  8
#define NPAIR (T_TOK*TOPK)   // 16384

#define STG_BYTES 32768             // A 128x128B + B 128x128B (fp16, BK=64), swizzled
#define NSTAGE 3
#define DYN_SMEM (NSTAGE*STG_BYTES + 1024)

// ---------------- device scratch (static, allocation-free) ----------------
__device__ int    g_topk_idx[NPAIR];
__device__ float  g_topk_w[NPAIR];
__device__ int    g_counts[NEXP];
__device__ int    g_list[NEXP*T_TOK];
__device__ __half g_xbuf_h[(size_t)T_TOK*HID];          // fp16 hidden
__device__ __half g_hbuf_h[(size_t)(NPAIR+128)*IDIM];   // fp16 silu(g)*u
__device__ float  g_outbuf[(size_t)NPAIR*HID];

// ---------------- helpers ----------------
__device__ __forceinline__ uint32_t packh2(float a, float b) {
    __half2 h = __floats2half2_rn(a, b);
    return *(uint32_t*)&h;
}
__device__ __forceinline__ void mma_f16(float* c, uint32_t a0, uint32_t a1, uint32_t a2, uint32_t a3,
                                        uint32_t b0, uint32_t b1) {
    asm volatile(
        "mma.sync.aligned.m16n8k16.row.col.f32.f16.f16.f32 "
        "{%0,%1,%2,%3}, {%4,%5,%6,%7}, {%8,%9}, {%0,%1,%2,%3};\n"
        : "+f"(c[0]), "+f"(c[1]), "+f"(c[2]), "+f"(c[3])
        : "r"(a0), "r"(a1), "r"(a2), "r"(a3), "r"(b0), "r"(b1));
}
__device__ __forceinline__ void cp_async16(uint32_t smem_addr, const void* gptr, int src_bytes) {
    asm volatile("cp.async.cg.shared.global [%0], [%1], 16, %2;\n"
                 :: "r"(smem_addr), "l"(gptr), "r"(src_bytes));
}
__device__ __forceinline__ void cp_commit() { asm volatile("cp.async.commit_group;\n"); }
template<int N> __device__ __forceinline__ void cp_wait() {
    asm volatile("cp.async.wait_group %0;\n" :: "n"(N));
}

// ---------------- 1. router (+ fused fp16 conversion of hidden) ------------
__global__ void router_kernel(const float* __restrict__ x, const float* __restrict__ gw) {
    __shared__ float Xs[16][68];
    __shared__ float Gs[64][68];
    __shared__ float Ls[16][64];
    const int tid = threadIdx.x;
    const int t0  = blockIdx.x * 16;
    const int tl  = tid & 15;
    const int eg  = tid >> 4;

    float acc[4] = {0.f, 0.f, 0.f, 0.f};

    for (int kk = 0; kk < HID; kk += 64) {
        {
            int r = tid >> 4, c = (tid & 15) * 4;
            float4 v = *(const float4*)(x + (size_t)(t0 + r) * HID + kk + c);
            Xs[r][c] = v.x; Xs[r][c+1] = v.y; Xs[r][c+2] = v.z; Xs[r][c+3] = v.w;
            uint2 hv;
            hv.x = packh2(v.x, v.y);
            hv.y = packh2(v.z, v.w);
            *(uint2*)(g_xbuf_h + (size_t)(t0 + r) * HID + kk + c) = hv;
        }
        #pragma unroll
        for (int i = 0; i < 4; i++) {
            int idx = i * 256 + tid;
            int r = idx >> 4, c = (idx & 15) * 4;
            float4 v = *(const float4*)(gw + (size_t)r * HID + kk + c);
            Gs[r][c] = v.x; Gs[r][c+1] = v.y; Gs[r][c+2] = v.z; Gs[r][c+3] = v.w;
        }
        __syncthreads();
        #pragma unroll 4
        for (int k = 0; k < 64; k += 4) {
            float4 xv = *(const float4*)&Xs[tl][k];
            #pragma unroll
            for (int j = 0; j < 4; j++) {
                float4 gv = *(const float4*)&Gs[eg*4 + j][k];
                acc[j] += xv.x*gv.x + xv.y*gv.y + xv.z*gv.z + xv.w*gv.w;
            }
        }
        __syncthreads();
    }
    #pragma unroll
    for (int j = 0; j < 4; j++) Ls[tl][eg*4 + j] = acc[j];
    __syncthreads();

    const int wid = tid >> 5, lane = tid & 31;
    for (int j = 0; j < 2; j++) {
        const int tok = wid * 2 + j;
        float v0 = Ls[tok][lane];
        float v1 = Ls[tok][lane + 32];
        bool s0 = false, s1 = false;
        float vals[8]; int idxs[8];
        #pragma unroll
        for (int r = 0; r < 8; r++) {
            float bv = -1e30f; int bi = 1 << 20;
            if (!s0) { bv = v0; bi = lane; }
            if (!s1 && (v1 > bv || (v1 == bv && lane + 32 < bi))) { bv = v1; bi = lane + 32; }
            #pragma unroll
            for (int o = 16; o > 0; o >>= 1) {
                float ov = __shfl_xor_sync(0xffffffffu, bv, o);
                int   oi = __shfl_xor_sync(0xffffffffu, bi, o);
                if (ov > bv || (ov == bv && oi < bi)) { bv = ov; bi = oi; }
            }
            vals[r] = bv; idxs[r] = bi;
            if (bi == lane)      s0 = true;
            if (bi == lane + 32) s1 = true;
        }
        if (lane == 0) {
            float m = vals[0];
            float w[8]; float sum = 0.f;
            #pragma unroll
            for (int r = 0; r < 8; r++) { w[r] = __expf(vals[r] - m); sum += w[r]; }
            float inv = 1.f / sum;
            int gt = t0 + tok;
            #pragma unroll
            for (int r = 0; r < 8; r++) {
                g_topk_idx[gt*TOPK + r] = idxs[r];
                g_topk_w  [gt*TOPK + r] = w[r] * inv;
            }
        }
    }
}

// ---------------- 2. bucketing ----------------
__global__ void bucket_kernel() {
    const int e = blockIdx.x;
    const int tid = threadIdx.x;
    __shared__ int warp_tot[8];
    __shared__ int base_s;
    if (tid == 0) base_s = 0;
    __syncthreads();
    const int wid = tid >> 5, lane = tid & 31;
    for (int t0 = 0; t0 < T_TOK; t0 += 256) {
        int t = t0 + tid;
        int slot = -1;
        #pragma unroll
        for (int k = 0; k < TOPK; k++)
            if (g_topk_idx[t*TOPK + k] == e) slot = k;
        unsigned m = __ballot_sync(0xffffffffu, slot >= 0);
        if (lane == 0) warp_tot[wid] = __popc(m);
        __syncthreads();
        int wbase = base_s;
        for (int i = 0; i < wid; i++) wbase += warp_tot[i];
        if (slot >= 0) {
            int pos = wbase + __popc(m & ((1u << lane) - 1u));
            g_list[e*T_TOK + pos] = t*TOPK + slot;
        }
        __syncthreads();
        if (tid == 0) {
            int tot = 0;
            for (int i = 0; i < 8; i++) tot += warp_tot[i];
            base_s += tot;
        }
        __syncthreads();
    }
    if (tid == 0) g_counts[e] = base_s;
}

// =====================================================================
// fp16 stage layout: rows 0..127 = A (128 x 64 half), rows 128..255 = B,
// 128 B/row; 16B chunk c of row r at byte r*128 + ((c ^ (r&7))*16).
// BK = 64. Row-granular tile truncation: warp skips m-subtiles beyond
// mtmax = ceil(rows_in_warp/16); cp.async skips rows >= ceil16(rows).
// =====================================================================

// ---------------- 3. GEMM1: h = silu(X Wg^T) * (X Wu^T) ----------------
__global__ void __launch_bounds__(256, 2)
gemm_gateup(const float* __restrict__ wg,
            const float* __restrict__ wu) {
    const int mb = blockIdx.x, nb = blockIdx.y, e = blockIdx.z;
    const int cnt = g_counts[e];
    if (mb * 128 >= cnt) return;

    extern __shared__ char smraw[];
    uint32_t sm0 = (uint32_t)__cvta_generic_to_shared(smraw);
    uint32_t smA = (sm0 + 1023u) & ~1023u;
    char*    smg = smraw + (smA - sm0);

    __shared__ int toks_s[128];
    __shared__ int cnt_s[NEXP];

    const int tid = threadIdx.x;
    if (tid < NEXP) cnt_s[tid] = g_counts[tid];
    if (tid < 128) {
        int m = mb * 128 + tid;
        toks_s[tid] = (m < cnt) ? (g_list[e*T_TOK + m] >> 3) : -1;
    }
    __syncthreads();
    int base = 0;
    for (int i = 0; i < e; i++) base += cnt_s[i];

    const int rows  = min(cnt - mb * 128, 128);
    const int rc16  = (rows + 15) & ~15;

    const int n0 = nb * 64;
    const float* wg_p = wg + ((size_t)e * IDIM + n0) * HID;
    const float* wu_p = wu + ((size_t)e * IDIM + n0) * HID;

    // A: cp.async fp16 chunks (4 per thread); skip fully-padded rows
    auto cpA = [&](int kt, int s) {
        const int kk = kt * 64;
        const uint32_t st = smA + (uint32_t)(s * STG_BYTES);
        #pragma unroll
        for (int it = 0; it < 4; it++) {
            int fid = it * 256 + tid;
            int r = fid >> 3, c = fid & 7;
            int tok = toks_s[r];
            if (tok >= 0)
                cp_async16(st + (uint32_t)(r * 128 + ((c ^ (r & 7)) * 16)),
                           g_xbuf_h + (size_t)tok * HID + kk + c * 8, 16);
            else if (r < rc16)
                cp_async16(st + (uint32_t)(r * 128 + ((c ^ (r & 7)) * 16)), g_xbuf_h, 0);
        }
    };
    uint32_t rBh[16];
    auto ldgB = [&](int kt) {
        const int kk = kt * 64;
        #pragma unroll
        for (int it = 0; it < 4; it++) {
            int fid = it * 256 + tid;
            int r = fid >> 3, c = fid & 7;
            const float* src = (r < 64) ? wg_p + (size_t)r * HID + kk + c * 8
                                        : wu_p + (size_t)(r - 64) * HID + kk + c * 8;
            float4 v0 = *(const float4*)src;
            float4 v1 = *(const float4*)(src + 4);
            rBh[it*4+0] = packh2(v0.x, v0.y);
            rBh[it*4+1] = packh2(v0.z, v0.w);
            rBh[it*4+2] = packh2(v1.x, v1.y);
            rBh[it*4+3] = packh2(v1.z, v1.w);
        }
    };
    auto stsB = [&](int s) {
        #pragma unroll
        for (int it = 0; it < 4; it++) {
            int fid = it * 256 + tid;
            int r = fid >> 3, c = fid & 7;
            *(uint4*)(smg + s * STG_BYTES + 16384 + r * 128 + ((c ^ (r & 7)) * 16))
                = make_uint4(rBh[it*4+0], rBh[it*4+1], rBh[it*4+2], rBh[it*4+3]);
        }
    };

    float cg[4][2][4], cu[4][2][4];
    #pragma unroll
    for (int a = 0; a < 4; a++)
        #pragma unroll
        for (int b = 0; b < 2; b++)
            #pragma unroll
            for (int c = 0; c < 4; c++) { cg[a][b][c] = 0.f; cu[a][b][c] = 0.f; }

    const int wid = tid >> 5, lane = tid & 31;
    const int wm = wid & 1, wn = wid >> 1;        // 2m x 4n
    const int grp = lane >> 2, tg = lane & 3;

    const int rows_w = max(0, min(rows - wm * 64, 64));
    const int mtmax  = (rows_w + 15) >> 4;

    const int KT = HID / 64;                       // 32
    ldgB(0);
    cpA(0, 0); cp_commit();
    stsB(0);
    cpA(1, 1); cp_commit();
    ldgB(1);

    for (int kt = 0; kt < KT; kt++) {
        cp_wait<1>();
        __syncthreads();                           // stage kt (A + B) visible; compute(kt-1) done
        if (kt + 1 < KT) stsB((kt + 1) % 3);
        if (kt + 2 < KT) { ldgB(kt + 2); cpA(kt + 2, (kt + 2) % 3); }
        cp_commit();

        const char* st = smg + (kt % 3) * STG_BYTES;
        if (mtmax > 0) {
            #pragma unroll
            for (int p = 0; p < 2; p++) {
                const int cA = ((2 * tg + p) ^ grp) * 16;
                uint4 Bg[2], Bu[2];
                #pragma unroll
                for (int nf = 0; nf < 2; nf++) {
                    int br = 128 + wn * 16 + nf * 8 + grp;
                    Bg[nf] = *(const uint4*)(st + br * 128 + cA);
                    Bu[nf] = *(const uint4*)(st + (br + 64) * 128 + cA);
                }
                #pragma unroll
                for (int mt = 0; mt < 4; mt++) {
                    if (mt < mtmax) {
                        int ar = wm * 64 + mt * 16 + grp;
                        uint4 Alo = *(const uint4*)(st + ar * 128 + cA);
                        uint4 Ahi = *(const uint4*)(st + (ar + 8) * 128 + cA);
                        #pragma unroll
                        for (int nf = 0; nf < 2; nf++) {
                            mma_f16(cg[mt][nf], Alo.x, Ahi.x, Alo.y, Ahi.y, Bg[nf].x, Bg[nf].y);
                            mma_f16(cu[mt][nf], Alo.x, Ahi.x, Alo.y, Ahi.y, Bu[nf].x, Bu[nf].y);
                        }
                        #pragma unroll
                        for (int nf = 0; nf < 2; nf++) {
                            mma_f16(cg[mt][nf], Alo.z, Ahi.z, Alo.w, Ahi.w, Bg[nf].z, Bg[nf].w);
                            mma_f16(cu[mt][nf], Alo.z, Ahi.z, Alo.w, Ahi.w, Bu[nf].z, Bu[nf].w);
                        }
                    }
                }
            }
        }
    }

    // ---- epilogue: silu(g)*u -> fp16 g_hbuf_h ----
    #pragma unroll
    for (int mt = 0; mt < 4; mt++) {
        #pragma unroll
        for (int hl = 0; hl < 2; hl++) {
            int row = wm * 64 + mt * 16 + hl * 8 + grp;
            int m = mb * 128 + row;
            if (m < cnt) {
                __half* hrow = g_hbuf_h + (size_t)(base + m) * IDIM + n0;
                #pragma unroll
                for (int nf = 0; nf < 2; nf++) {
                    int col = wn * 16 + nf * 8 + tg * 2;
                    float g0 = cg[mt][nf][hl*2 + 0], u0 = cu[mt][nf][hl*2 + 0];
                    float g1 = cg[mt][nf][hl*2 + 1], u1 = cu[mt][nf][hl*2 + 1];
                    float h0 = g0 * u0 / (1.f + __expf(-g0));
                    float h1 = g1 * u1 / (1.f + __expf(-g1));
                    *(uint32_t*)(hrow + col) = packh2(h0, h1);
                }
            }
        }
    }
}

// ---------------- 4. GEMM2: y = (h Wd^T) * combine_w -> g_outbuf ----------
__global__ void __launch_bounds__(256, 2)
gemm_down(const float* __restrict__ wd) {
    const int mb = blockIdx.x, nb = blockIdx.y, e = blockIdx.z;
    const int cnt = g_counts[e];
    if (mb * 128 >= cnt) return;

    extern __shared__ char smraw[];
    uint32_t sm0 = (uint32_t)__cvta_generic_to_shared(smraw);
    uint32_t smA = (sm0 + 1023u) & ~1023u;
    char*    smg = smraw + (smA - sm0);

    __shared__ int pairs_s[128];
    __shared__ int cnt_s[NEXP];

    const int tid = threadIdx.x;
    if (tid < NEXP) cnt_s[tid] = g_counts[tid];
    if (tid < 128) {
        int m = mb * 128 + tid;
        pairs_s[tid] = (m < cnt) ? g_list[e*T_TOK + m] : -1;
    }
    __syncthreads();
    int base = 0;
    for (int i = 0; i < e; i++) base += cnt_s[i];

    const int rows = min(cnt - mb * 128, 128);
    const int rc16 = (rows + 15) & ~15;

    const int n0 = nb * 128;
    const float*  wd_p  = wd + ((size_t)e * HID + n0) * IDIM;
    const __half* arow0 = g_hbuf_h + (size_t)(base + mb * 128) * IDIM;

    auto cpA = [&](int kt, int s) {
        const int kk = kt * 64;
        const uint32_t st = smA + (uint32_t)(s * STG_BYTES);
        #pragma unroll
        for (int it = 0; it < 4; it++) {
            int fid = it * 256 + tid;
            int r = fid >> 3, c = fid & 7;
            if (pairs_s[r] >= 0)
                cp_async16(st + (uint32_t)(r * 128 + ((c ^ (r & 7)) * 16)),
                           arow0 + (size_t)r * IDIM + kk + c * 8, 16);
            else if (r < rc16)
                cp_async16(st + (uint32_t)(r * 128 + ((c ^ (r & 7)) * 16)), g_hbuf_h, 0);
        }
    };
    uint32_t rBh[16];
    auto ldgB = [&](int kt) {
        const int kk = kt * 64;
        #pragma unroll
        for (int it = 0; it < 4; it++) {
            int fid = it * 256 + tid;
            int r = fid >> 3, c = fid & 7;
            const float* src = wd_p + (size_t)r * IDIM + kk + c * 8;
            float4 v0 = *(const float4*)src;
            float4 v1 = *(const float4*)(src + 4);
            rBh[it*4+0] = packh2(v0.x, v0.y);
            rBh[it*4+1] = packh2(v0.z, v0.w);
            rBh[it*4+2] = packh2(v1.x, v1.y);
            rBh[it*4+3] = packh2(v1.z, v1.w);
        }
    };
    auto stsB = [&](int s) {
        #pragma unroll
        for (int it = 0; it < 4; it++) {
            int fid = it * 256 + tid;
            int r = fid >> 3, c = fid & 7;
            *(uint4*)(smg + s * STG_BYTES + 16384 + r * 128 + ((c ^ (r & 7)) * 16))
                = make_uint4(rBh[it*4+0], rBh[it*4+1], rBh[it*4+2], rBh[it*4+3]);
        }
    };

    float cd[4][4][4];
    #pragma unroll
    for (int a = 0; a < 4; a++)
        #pragma unroll
        for (int b = 0; b < 4; b++)
            #pragma unroll
            for (int c = 0; c < 4; c++) cd[a][b][c] = 0.f;

    const int wid = tid >> 5, lane = tid & 31;
    const int wm = wid & 1, wn = wid >> 1;
    const int grp = lane >> 2, tg = lane & 3;

    const int rows_w = max(0, min(rows - wm * 64, 64));
    const int mtmax  = (rows_w + 15) >> 4;

    const int KT = IDIM / 64;                      // 12
    ldgB(0);
    cpA(0, 0); cp_commit();
    stsB(0);
    cpA(1, 1); cp_commit();
    ldgB(1);

    for (int kt = 0; kt < KT; kt++) {
        cp_wait<1>();
        __syncthreads();
        if (kt + 1 < KT) stsB((kt + 1) % 3);
        if (kt + 2 < KT) { ldgB(kt + 2); cpA(kt + 2, (kt + 2) % 3); }
        cp_commit();

        const char* st = smg + (kt % 3) * STG_BYTES;
        if (mtmax > 0) {
            #pragma unroll
            for (int p = 0; p < 2; p++) {
                const int cA = ((2 * tg + p) ^ grp) * 16;
                uint4 Bw[4];
                #pragma unroll
                for (int nf = 0; nf < 4; nf++) {
                    int br = 128 + wn * 32 + nf * 8 + grp;
                    Bw[nf] = *(const uint4*)(st + br * 128 + cA);
                }
                #pragma unroll
                for (int mt = 0; mt < 4; mt++) {
                    if (mt < mtmax) {
                        int ar = wm * 64 + mt * 16 + grp;
                        uint4 Alo = *(const uint4*)(st + ar * 128 + cA);
                        uint4 Ahi = *(const uint4*)(st + (ar + 8) * 128 + cA);
                        #pragma unroll
                        for (int nf = 0; nf < 4; nf++)
                            mma_f16(cd[mt][nf], Alo.x, Ahi.x, Alo.y, Ahi.y, Bw[nf].x, Bw[nf].y);
                        #pragma unroll
                        for (int nf = 0; nf < 4; nf++)
                            mma_f16(cd[mt][nf], Alo.z, Ahi.z, Alo.w, Ahi.w, Bw[nf].z, Bw[nf].w);
                    }
                }
            }
        }
    }

    // ---- epilogue: scale by combine weight, streaming-store per-pair row ----
    #pragma unroll
    for (int mt = 0; mt < 4; mt++) {
        #pragma unroll
        for (int hl = 0; hl < 2; hl++) {
            int row = wm * 64 + mt * 16 + hl * 8 + grp;
            int pair = pairs_s[row];
            if (pair >= 0) {
                float w = g_topk_w[pair];
                float* orow = g_outbuf + (size_t)pair * HID + n0;
                #pragma unroll
                for (int nf = 0; nf < 4; nf++) {
                    int col = wn * 32 + nf * 8 + tg * 2;
                    float2 ov;
                    ov.x = cd[mt][nf][hl*2 + 0] * w;
                    ov.y = cd[mt][nf][hl*2 + 1] * w;
                    __stcs((float2*)(orow + col), ov);
                }
            }
        }
    }
}

// ---------------- 5. final reduce ----------------
__global__ void reduce_kernel(float* __restrict__ out) {
    int idx = blockIdx.x * blockDim.x + threadIdx.x;
    int t = idx >> 9;
    int h4 = idx & 511;
    const float4* ob = (const float4*)g_outbuf;
    float4 s = __ldcs(&ob[(size_t)(t * TOPK) * (HID/4) + h4]);
    #pragma unroll
    for (int k = 1; k < TOPK; k++) {
        float4 v = __ldcs(&ob[(size_t)(t * TOPK + k) * (HID/4) + h4]);
        s.x += v.x; s.y += v.y; s.z += v.z; s.w += v.w;
    }
    ((float4*)out)[idx] = s;
}

// ---------------- launch ----------------
extern "C" void kernel_launch(void* const* d_in, const int* in_sizes, int n_in,
                              void* d_out, int out_size) {
    (void)in_sizes; (void)n_in; (void)out_size;
    const float* hidden = (const float*)d_in[0];
    const float* gate_w = (const float*)d_in[1];
    const float* w_gate = (const float*)d_in[2];
    const float* w_up   = (const float*)d_in[3];
    const float* w_down = (const float*)d_in[4];
    float* out = (float*)d_out;

    cudaFuncSetAttribute(gemm_gateup, cudaFuncAttributeMaxDynamicSharedMemorySize, DYN_SMEM);
    cudaFuncSetAttribute(gemm_down,   cudaFuncAttributeMaxDynamicSharedMemorySize, DYN_SMEM);

    router_kernel<<<T_TOK/16, 256>>>(hidden, gate_w);                 // idx 0
    bucket_kernel<<<NEXP, 256>>>();                                   // idx 1
    gemm_gateup<<<dim3(T_TOK/128, IDIM/64, NEXP), 256, DYN_SMEM>>>(w_gate, w_up);  // idx 2
    gemm_down  <<<dim3(T_TOK/128, HID/128, NEXP), 256, DYN_SMEM>>>(w_down);        // idx 3
    reduce_kernel<<<(T_TOK*(HID/4))/256, 256>>>(out);
}

// round 14
// speedup vs baseline: 1.0432x; 1.0432x over previous
#include <cuda_runtime.h>
#include <cuda_fp16.h>
#include <cstdint>

#define T_TOK 2048
#define HID   2048
#define NEXP  64
#define IDIM  768
#define TOPK  8
#define NPAIR (T_TOK*TOPK)   // 16384

#define STG_BYTES 32768             // A 128x128B + B 128x128B (fp16, BK=64), swizzled
#define NSTAGE 3
#define DYN_SMEM (NSTAGE*STG_BYTES + 1024)

// ---------------- device scratch (static, allocation-free) ----------------
__device__ int    g_topk_idx[NPAIR];
__device__ float  g_topk_w[NPAIR];
__device__ int    g_counts[NEXP];
__device__ int    g_list[NEXP*T_TOK];
__device__ __half g_xbuf_h[(size_t)T_TOK*HID];          // fp16 hidden
__device__ __half g_hbuf_h[(size_t)(NPAIR+128)*IDIM];   // fp16 silu(g)*u
__device__ float  g_outbuf[(size_t)NPAIR*HID];

// ---------------- helpers ----------------
__device__ __forceinline__ uint32_t packh2(float a, float b) {
    __half2 h = __floats2half2_rn(a, b);
    return *(uint32_t*)&h;
}
__device__ __forceinline__ void mma_f16(float* c, uint32_t a0, uint32_t a1, uint32_t a2, uint32_t a3,
                                        uint32_t b0, uint32_t b1) {
    asm volatile(
        "mma.sync.aligned.m16n8k16.row.col.f32.f16.f16.f32 "
        "{%0,%1,%2,%3}, {%4,%5,%6,%7}, {%8,%9}, {%0,%1,%2,%3};\n"
        : "+f"(c[0]), "+f"(c[1]), "+f"(c[2]), "+f"(c[3])
        : "r"(a0), "r"(a1), "r"(a2), "r"(a3), "r"(b0), "r"(b1));
}
__device__ __forceinline__ void cp_async16(uint32_t smem_addr, const void* gptr, int src_bytes) {
    asm volatile("cp.async.cg.shared.global [%0], [%1], 16, %2;\n"
                 :: "r"(smem_addr), "l"(gptr), "r"(src_bytes));
}
__device__ __forceinline__ void cp_commit() { asm volatile("cp.async.commit_group;\n"); }
template<int N> __device__ __forceinline__ void cp_wait() {
    asm volatile("cp.async.wait_group %0;\n" :: "n"(N));
}

// ---------------- 1. router (+ fused fp16 conversion of hidden) ------------
__global__ void router_kernel(const float* __restrict__ x, const float* __restrict__ gw) {
    __shared__ float Xs[16][68];
    __shared__ float Gs[64][68];
    __shared__ float Ls[16][64];
    const int tid = threadIdx.x;
    const int t0  = blockIdx.x * 16;
    const int tl  = tid & 15;
    const int eg  = tid >> 4;

    float acc[4] = {0.f, 0.f, 0.f, 0.f};

    for (int kk = 0; kk < HID; kk += 64) {
        {
            int r = tid >> 4, c = (tid & 15) * 4;
            float4 v = *(const float4*)(x + (size_t)(t0 + r) * HID + kk + c);
            Xs[r][c] = v.x; Xs[r][c+1] = v.y; Xs[r][c+2] = v.z; Xs[r][c+3] = v.w;
            uint2 hv;
            hv.x = packh2(v.x, v.y);
            hv.y = packh2(v.z, v.w);
            *(uint2*)(g_xbuf_h + (size_t)(t0 + r) * HID + kk + c) = hv;
        }
        #pragma unroll
        for (int i = 0; i < 4; i++) {
            int idx = i * 256 + tid;
            int r = idx >> 4, c = (idx & 15) * 4;
            float4 v = *(const float4*)(gw + (size_t)r * HID + kk + c);
            Gs[r][c] = v.x; Gs[r][c+1] = v.y; Gs[r][c+2] = v.z; Gs[r][c+3] = v.w;
        }
        __syncthreads();
        #pragma unroll 4
        for (int k = 0; k < 64; k += 4) {
            float4 xv = *(const float4*)&Xs[tl][k];
            #pragma unroll
            for (int j = 0; j < 4; j++) {
                float4 gv = *(const float4*)&Gs[eg*4 + j][k];
                acc[j] += xv.x*gv.x + xv.y*gv.y + xv.z*gv.z + xv.w*gv.w;
            }
        }
        __syncthreads();
    }
    #pragma unroll
    for (int j = 0; j < 4; j++) Ls[tl][eg*4 + j] = acc[j];
    __syncthreads();

    const int wid = tid >> 5, lane = tid & 31;
    for (int j = 0; j < 2; j++) {
        const int tok = wid * 2 + j;
        float v0 = Ls[tok][lane];
        float v1 = Ls[tok][lane + 32];
        bool s0 = false, s1 = false;
        float vals[8]; int idxs[8];
        #pragma unroll
        for (int r = 0; r < 8; r++) {
            float bv = -1e30f; int bi = 1 << 20;
            if (!s0) { bv = v0; bi = lane; }
            if (!s1 && (v1 > bv || (v1 == bv && lane + 32 < bi))) { bv = v1; bi = lane + 32; }
            #pragma unroll
            for (int o = 16; o > 0; o >>= 1) {
                float ov = __shfl_xor_sync(0xffffffffu, bv, o);
                int   oi = __shfl_xor_sync(0xffffffffu, bi, o);
                if (ov > bv || (ov == bv && oi < bi)) { bv = ov; bi = oi; }
            }
            vals[r] = bv; idxs[r] = bi;
            if (bi == lane)      s0 = true;
            if (bi == lane + 32) s1 = true;
        }
        if (lane == 0) {
            float m = vals[0];
            float w[8]; float sum = 0.f;
            #pragma unroll
            for (int r = 0; r < 8; r++) { w[r] = __expf(vals[r] - m); sum += w[r]; }
            float inv = 1.f / sum;
            int gt = t0 + tok;
            #pragma unroll
            for (int r = 0; r < 8; r++) {
                g_topk_idx[gt*TOPK + r] = idxs[r];
                g_topk_w  [gt*TOPK + r] = w[r] * inv;
            }
        }
    }
}

// ---------------- 2. bucketing ----------------
__global__ void bucket_kernel() {
    const int e = blockIdx.x;
    const int tid = threadIdx.x;
    __shared__ int warp_tot[8];
    __shared__ int base_s;
    if (tid == 0) base_s = 0;
    __syncthreads();
    const int wid = tid >> 5, lane = tid & 31;
    for (int t0 = 0; t0 < T_TOK; t0 += 256) {
        int t = t0 + tid;
        int slot = -1;
        #pragma unroll
        for (int k = 0; k < TOPK; k++)
            if (g_topk_idx[t*TOPK + k] == e) slot = k;
        unsigned m = __ballot_sync(0xffffffffu, slot >= 0);
        if (lane == 0) warp_tot[wid] = __popc(m);
        __syncthreads();
        int wbase = base_s;
        for (int i = 0; i < wid; i++) wbase += warp_tot[i];
        if (slot >= 0) {
            int pos = wbase + __popc(m & ((1u << lane) - 1u));
            g_list[e*T_TOK + pos] = t*TOPK + slot;
        }
        __syncthreads();
        if (tid == 0) {
            int tot = 0;
            for (int i = 0; i < 8; i++) tot += warp_tot[i];
            base_s += tot;
        }
        __syncthreads();
    }
    if (tid == 0) g_counts[e] = base_s;
}

// =====================================================================
// fp16 stage layout: rows 0..127 = A (128 x 64 half), rows 128..255 = B,
// 128 B/row; 16B chunk c of row r at byte r*128 + ((c ^ (r&7))*16).
// Full tiles run the unconditional (R12) MMA block; tail tiles branch
// (warp-uniform, loop-invariant) into a predicated block. Barriers stay
// outside the branch. Padded rows get NO cp.async (stale smem feeds only
// rows discarded at the m<cnt epilogue guard).
// =====================================================================

// ---------------- 3. GEMM1: h = silu(X Wg^T) * (X Wu^T) ----------------
__global__ void __launch_bounds__(256, 2)
gemm_gateup(const float* __restrict__ wg,
            const float* __restrict__ wu) {
    const int mb = blockIdx.x, nb = blockIdx.y, e = blockIdx.z;
    const int cnt = g_counts[e];
    if (mb * 128 >= cnt) return;

    extern __shared__ char smraw[];
    uint32_t sm0 = (uint32_t)__cvta_generic_to_shared(smraw);
    uint32_t smA = (sm0 + 1023u) & ~1023u;
    char*    smg = smraw + (smA - sm0);

    __shared__ int toks_s[128];
    __shared__ int cnt_s[NEXP];

    const int tid = threadIdx.x;
    if (tid < NEXP) cnt_s[tid] = g_counts[tid];
    if (tid < 128) {
        int m = mb * 128 + tid;
        toks_s[tid] = (m < cnt) ? (g_list[e*T_TOK + m] >> 3) : -1;
    }
    __syncthreads();
    int base = 0;
    for (int i = 0; i < e; i++) base += cnt_s[i];

    const int rows = min(cnt - mb * 128, 128);

    const int n0 = nb * 64;
    const float* wg_p = wg + ((size_t)e * IDIM + n0) * HID;
    const float* wu_p = wu + ((size_t)e * IDIM + n0) * HID;

    // A: cp.async fp16 chunks; padded rows get nothing (results discarded)
    auto cpA = [&](int kt, int s) {
        const int kk = kt * 64;
        const uint32_t st = smA + (uint32_t)(s * STG_BYTES);
        #pragma unroll
        for (int it = 0; it < 4; it++) {
            int fid = it * 256 + tid;
            int r = fid >> 3, c = fid & 7;
            int tok = toks_s[r];
            if (tok >= 0)
                cp_async16(st + (uint32_t)(r * 128 + ((c ^ (r & 7)) * 16)),
                           g_xbuf_h + (size_t)tok * HID + kk + c * 8, 16);
        }
    };
    uint32_t rBh[16];
    auto ldgB = [&](int kt) {
        const int kk = kt * 64;
        #pragma unroll
        for (int it = 0; it < 4; it++) {
            int fid = it * 256 + tid;
            int r = fid >> 3, c = fid & 7;
            const float* src = (r < 64) ? wg_p + (size_t)r * HID + kk + c * 8
                                        : wu_p + (size_t)(r - 64) * HID + kk + c * 8;
            float4 v0 = *(const float4*)src;
            float4 v1 = *(const float4*)(src + 4);
            rBh[it*4+0] = packh2(v0.x, v0.y);
            rBh[it*4+1] = packh2(v0.z, v0.w);
            rBh[it*4+2] = packh2(v1.x, v1.y);
            rBh[it*4+3] = packh2(v1.z, v1.w);
        }
    };
    auto stsB = [&](int s) {
        #pragma unroll
        for (int it = 0; it < 4; it++) {
            int fid = it * 256 + tid;
            int r = fid >> 3, c = fid & 7;
            *(uint4*)(smg + s * STG_BYTES + 16384 + r * 128 + ((c ^ (r & 7)) * 16))
                = make_uint4(rBh[it*4+0], rBh[it*4+1], rBh[it*4+2], rBh[it*4+3]);
        }
    };

    float cg[4][2][4], cu[4][2][4];
    #pragma unroll
    for (int a = 0; a < 4; a++)
        #pragma unroll
        for (int b = 0; b < 2; b++)
            #pragma unroll
            for (int c = 0; c < 4; c++) { cg[a][b][c] = 0.f; cu[a][b][c] = 0.f; }

    const int wid = tid >> 5, lane = tid & 31;
    const int wm = wid & 1, wn = wid >> 1;        // 2m x 4n
    const int grp = lane >> 2, tg = lane & 3;

    const int rows_w = max(0, min(rows - wm * 64, 64));
    const int mtmax  = (rows_w + 15) >> 4;
    const bool full  = (rows_w == 64);

    const int KT = HID / 64;                       // 32
    ldgB(0);
    cpA(0, 0); cp_commit();
    stsB(0);
    cpA(1, 1); cp_commit();
    ldgB(1);

    for (int kt = 0; kt < KT; kt++) {
        cp_wait<1>();
        __syncthreads();                           // stage kt visible; compute(kt-1) done
        if (kt + 1 < KT) stsB((kt + 1) % 3);
        if (kt + 2 < KT) { ldgB(kt + 2); cpA(kt + 2, (kt + 2) % 3); }
        cp_commit();

        const char* st = smg + (kt % 3) * STG_BYTES;
        if (full) {
            // ---- exact R12 unconditional block (full tiles) ----
            #pragma unroll
            for (int p = 0; p < 2; p++) {
                const int cA = ((2 * tg + p) ^ grp) * 16;
                uint4 Bg[2], Bu[2];
                #pragma unroll
                for (int nf = 0; nf < 2; nf++) {
                    int br = 128 + wn * 16 + nf * 8 + grp;
                    Bg[nf] = *(const uint4*)(st + br * 128 + cA);
                    Bu[nf] = *(const uint4*)(st + (br + 64) * 128 + cA);
                }
                #pragma unroll
                for (int mt = 0; mt < 4; mt++) {
                    int ar = wm * 64 + mt * 16 + grp;
                    uint4 Alo = *(const uint4*)(st + ar * 128 + cA);
                    uint4 Ahi = *(const uint4*)(st + (ar + 8) * 128 + cA);
                    #pragma unroll
                    for (int nf = 0; nf < 2; nf++) {
                        mma_f16(cg[mt][nf], Alo.x, Ahi.x, Alo.y, Ahi.y, Bg[nf].x, Bg[nf].y);
                        mma_f16(cu[mt][nf], Alo.x, Ahi.x, Alo.y, Ahi.y, Bu[nf].x, Bu[nf].y);
                    }
                    #pragma unroll
                    for (int nf = 0; nf < 2; nf++) {
                        mma_f16(cg[mt][nf], Alo.z, Ahi.z, Alo.w, Ahi.w, Bg[nf].z, Bg[nf].w);
                        mma_f16(cu[mt][nf], Alo.z, Ahi.z, Alo.w, Ahi.w, Bu[nf].z, Bu[nf].w);
                    }
                }
            }
        } else if (mtmax > 0) {
            // ---- predicated block (tail tiles only) ----
            #pragma unroll
            for (int p = 0; p < 2; p++) {
                const int cA = ((2 * tg + p) ^ grp) * 16;
                uint4 Bg[2], Bu[2];
                #pragma unroll
                for (int nf = 0; nf < 2; nf++) {
                    int br = 128 + wn * 16 + nf * 8 + grp;
                    Bg[nf] = *(const uint4*)(st + br * 128 + cA);
                    Bu[nf] = *(const uint4*)(st + (br + 64) * 128 + cA);
                }
                #pragma unroll
                for (int mt = 0; mt < 4; mt++) {
                    if (mt < mtmax) {
                        int ar = wm * 64 + mt * 16 + grp;
                        uint4 Alo = *(const uint4*)(st + ar * 128 + cA);
                        uint4 Ahi = *(const uint4*)(st + (ar + 8) * 128 + cA);
                        #pragma unroll
                        for (int nf = 0; nf < 2; nf++) {
                            mma_f16(cg[mt][nf], Alo.x, Ahi.x, Alo.y, Ahi.y, Bg[nf].x, Bg[nf].y);
                            mma_f16(cu[mt][nf], Alo.x, Ahi.x, Alo.y, Ahi.y, Bu[nf].x, Bu[nf].y);
                        }
                        #pragma unroll
                        for (int nf = 0; nf < 2; nf++) {
                            mma_f16(cg[mt][nf], Alo.z, Ahi.z, Alo.w, Ahi.w, Bg[nf].z, Bg[nf].w);
                            mma_f16(cu[mt][nf], Alo.z, Ahi.z, Alo.w, Ahi.w, Bu[nf].z, Bu[nf].w);
                        }
                    }
                }
            }
        }
    }

    // ---- epilogue: silu(g)*u -> fp16 g_hbuf_h ----
    #pragma unroll
    for (int mt = 0; mt < 4; mt++) {
        #pragma unroll
        for (int hl = 0; hl < 2; hl++) {
            int row = wm * 64 + mt * 16 + hl * 8 + grp;
            int m = mb * 128 + row;
            if (m < cnt) {
                __half* hrow = g_hbuf_h + (size_t)(base + m) * IDIM + n0;
                #pragma unroll
                for (int nf = 0; nf < 2; nf++) {
                    int col = wn * 16 + nf * 8 + tg * 2;
                    float g0 = cg[mt][nf][hl*2 + 0], u0 = cu[mt][nf][hl*2 + 0];
                    float g1 = cg[mt][nf][hl*2 + 1], u1 = cu[mt][nf][hl*2 + 1];
                    float h0 = g0 * u0 / (1.f + __expf(-g0));
                    float h1 = g1 * u1 / (1.f + __expf(-g1));
                    *(uint32_t*)(hrow + col) = packh2(h0, h1);
                }
            }
        }
    }
}

// ---------------- 4. GEMM2: y = (h Wd^T) * combine_w -> g_outbuf ----------
__global__ void __launch_bounds__(256, 2)
gemm_down(const float* __restrict__ wd) {
    const int mb = blockIdx.x, nb = blockIdx.y, e = blockIdx.z;
    const int cnt = g_counts[e];
    if (mb * 128 >= cnt) return;

    extern __shared__ char smraw[];
    uint32_t sm0 = (uint32_t)__cvta_generic_to_shared(smraw);
    uint32_t smA = (sm0 + 1023u) & ~1023u;
    char*    smg = smraw + (smA - sm0);

    __shared__ int pairs_s[128];
    __shared__ int cnt_s[NEXP];

    const int tid = threadIdx.x;
    if (tid < NEXP) cnt_s[tid] = g_counts[tid];
    if (tid < 128) {
        int m = mb * 128 + tid;
        pairs_s[tid] = (m < cnt) ? g_list[e*T_TOK + m] : -1;
    }
    __syncthreads();
    int base = 0;
    for (int i = 0; i < e; i++) base += cnt_s[i];

    const int rows = min(cnt - mb * 128, 128);

    const int n0 = nb * 128;
    const float*  wd_p  = wd + ((size_t)e * HID + n0) * IDIM;
    const __half* arow0 = g_hbuf_h + (size_t)(base + mb * 128) * IDIM;

    auto cpA = [&](int kt, int s) {
        const int kk = kt * 64;
        const uint32_t st = smA + (uint32_t)(s * STG_BYTES);
        #pragma unroll
        for (int it = 0; it < 4; it++) {
            int fid = it * 256 + tid;
            int r = fid >> 3, c = fid & 7;
            if (pairs_s[r] >= 0)
                cp_async16(st + (uint32_t)(r * 128 + ((c ^ (r & 7)) * 16)),
                           arow0 + (size_t)r * IDIM + kk + c * 8, 16);
        }
    };
    uint32_t rBh[16];
    auto ldgB = [&](int kt) {
        const int kk = kt * 64;
        #pragma unroll
        for (int it = 0; it < 4; it++) {
            int fid = it * 256 + tid;
            int r = fid >> 3, c = fid & 7;
            const float* src = wd_p + (size_t)r * IDIM + kk + c * 8;
            float4 v0 = *(const float4*)src;
            float4 v1 = *(const float4*)(src + 4);
            rBh[it*4+0] = packh2(v0.x, v0.y);
            rBh[it*4+1] = packh2(v0.z, v0.w);
            rBh[it*4+2] = packh2(v1.x, v1.y);
            rBh[it*4+3] = packh2(v1.z, v1.w);
        }
    };
    auto stsB = [&](int s) {
        #pragma unroll
        for (int it = 0; it < 4; it++) {
            int fid = it * 256 + tid;
            int r = fid >> 3, c = fid & 7;
            *(uint4*)(smg + s * STG_BYTES + 16384 + r * 128 + ((c ^ (r & 7)) * 16))
                = make_uint4(rBh[it*4+0], rBh[it*4+1], rBh[it*4+2], rBh[it*4+3]);
        }
    };

    float cd[4][4][4];
    #pragma unroll
    for (int a = 0; a < 4; a++)
        #pragma unroll
        for (int b = 0; b < 4; b++)
            #pragma unroll
            for (int c = 0; c < 4; c++) cd[a][b][c] = 0.f;

    const int wid = tid >> 5, lane = tid & 31;
    const int wm = wid & 1, wn = wid >> 1;
    const int grp = lane >> 2, tg = lane & 3;

    const int rows_w = max(0, min(rows - wm * 64, 64));
    const int mtmax  = (rows_w + 15) >> 4;
    const bool full  = (rows_w == 64);

    const int KT = IDIM / 64;                      // 12
    ldgB(0);
    cpA(0, 0); cp_commit();
    stsB(0);
    cpA(1, 1); cp_commit();
    ldgB(1);

    for (int kt = 0; kt < KT; kt++) {
        cp_wait<1>();
        __syncthreads();
        if (kt + 1 < KT) stsB((kt + 1) % 3);
        if (kt + 2 < KT) { ldgB(kt + 2); cpA(kt + 2, (kt + 2) % 3); }
        cp_commit();

        const char* st = smg + (kt % 3) * STG_BYTES;
        if (full) {
            // ---- exact R12 unconditional block ----
            #pragma unroll
            for (int p = 0; p < 2; p++) {
                const int cA = ((2 * tg + p) ^ grp) * 16;
                uint4 Bw[4];
                #pragma unroll
                for (int nf = 0; nf < 4; nf++) {
                    int br = 128 + wn * 32 + nf * 8 + grp;
                    Bw[nf] = *(const uint4*)(st + br * 128 + cA);
                }
                #pragma unroll
                for (int mt = 0; mt < 4; mt++) {
                    int ar = wm * 64 + mt * 16 + grp;
                    uint4 Alo = *(const uint4*)(st + ar * 128 + cA);
                    uint4 Ahi = *(const uint4*)(st + (ar + 8) * 128 + cA);
                    #pragma unroll
                    for (int nf = 0; nf < 4; nf++)
                        mma_f16(cd[mt][nf], Alo.x, Ahi.x, Alo.y, Ahi.y, Bw[nf].x, Bw[nf].y);
                    #pragma unroll
                    for (int nf = 0; nf < 4; nf++)
                        mma_f16(cd[mt][nf], Alo.z, Ahi.z, Alo.w, Ahi.w, Bw[nf].z, Bw[nf].w);
                }
            }
        } else if (mtmax > 0) {
            // ---- predicated block (tail tiles only) ----
            #pragma unroll
            for (int p = 0; p < 2; p++) {
                const int cA = ((2 * tg + p) ^ grp) * 16;
                uint4 Bw[4];
                #pragma unroll
                for (int nf = 0; nf < 4; nf++) {
                    int br = 128 + wn * 32 + nf * 8 + grp;
                    Bw[nf] = *(const uint4*)(st + br * 128 + cA);
                }
                #pragma unroll
                for (int mt = 0; mt < 4; mt++) {
                    if (mt < mtmax) {
                        int ar = wm * 64 + mt * 16 + grp;
                        uint4 Alo = *(const uint4*)(st + ar * 128 + cA);
                        uint4 Ahi = *(const uint4*)(st + (ar + 8) * 128 + cA);
                        #pragma unroll
                        for (int nf = 0; nf < 4; nf++)
                            mma_f16(cd[mt][nf], Alo.x, Ahi.x, Alo.y, Ahi.y, Bw[nf].x, Bw[nf].y);
                        #pragma unroll
                        for (int nf = 0; nf < 4; nf++)
                            mma_f16(cd[mt][nf], Alo.z, Ahi.z, Alo.w, Ahi.w, Bw[nf].z, Bw[nf].w);
                    }
                }
            }
        }
    }

    // ---- epilogue: scale by combine weight, streaming-store per-pair row ----
    #pragma unroll
    for (int mt = 0; mt < 4; mt++) {
        #pragma unroll
        for (int hl = 0; hl < 2; hl++) {
            int row = wm * 64 + mt * 16 + hl * 8 + grp;
            int pair = pairs_s[row];
            if (pair >= 0) {
                float w = g_topk_w[pair];
                float* orow = g_outbuf + (size_t)pair * HID + n0;
                #pragma unroll
                for (int nf = 0; nf < 4; nf++) {
                    int col = wn * 32 + nf * 8 + tg * 2;
                    float2 ov;
                    ov.x = cd[mt][nf][hl*2 + 0] * w;
                    ov.y = cd[mt][nf][hl*2 + 1] * w;
                    __stcs((float2*)(orow + col), ov);
                }
            }
        }
    }
}

// ---------------- 5. final reduce ----------------
__global__ void reduce_kernel(float* __restrict__ out) {
    int idx = blockIdx.x * blockDim.x + threadIdx.x;
    int t = idx >> 9;
    int h4 = idx & 511;
    const float4* ob = (const float4*)g_outbuf;
    float4 s = __ldcs(&ob[(size_t)(t * TOPK) * (HID/4) + h4]);
    #pragma unroll
    for (int k = 1; k < TOPK; k++) {
        float4 v = __ldcs(&ob[(size_t)(t * TOPK + k) * (HID/4) + h4]);
        s.x += v.x; s.y += v.y; s.z += v.z; s.w += v.w;
    }
    ((float4*)out)[idx] = s;
}

// ---------------- launch ----------------
extern "C" void kernel_launch(void* const* d_in, const int* in_sizes, int n_in,
                              void* d_out, int out_size) {
    (void)in_sizes; (void)n_in; (void)out_size;
    const float* hidden = (const float*)d_in[0];
    const float* gate_w = (const float*)d_in[1];
    const float* w_gate = (const float*)d_in[2];
    const float* w_up   = (const float*)d_in[3];
    const float* w_down = (const float*)d_in[4];
    float* out = (float*)d_out;

    cudaFuncSetAttribute(gemm_gateup, cudaFuncAttributeMaxDynamicSharedMemorySize, DYN_SMEM);
    cudaFuncSetAttribute(gemm_down,   cudaFuncAttributeMaxDynamicSharedMemorySize, DYN_SMEM);

    router_kernel<<<T_TOK/16, 256>>>(hidden, gate_w);                 // idx 0
    bucket_kernel<<<NEXP, 256>>>();                                   // idx 1
    gemm_gateup<<<dim3(T_TOK/128, IDIM/64, NEXP), 256, DYN_SMEM>>>(w_gate, w_up);  // idx 2
    gemm_down  <<<dim3(T_TOK/128, HID/128, NEXP), 256, DYN_SMEM>>>(w_down);        // idx 3
    reduce_kernel<<<(T_TOK*(HID/4))/256, 256>>>(out);
}

// round 16
// speedup vs baseline: 1.1027x; 1.0570x over previous
#include <cuda_runtime.h>
#include <cuda_fp16.h>
#include <cstdint>

#define T_TOK 2048
#define HID   2048
#define NEXP  64
#define IDIM  768
#define TOPK  8
#define NPAIR (T_TOK*TOPK)   // 16384

#define STG_A 32768                 // A 256 rows x 128B (fp16 BK=64), swizzled
#define STG_B 16384                 // B 128 rows x 128B
#define STG   (STG_A + STG_B)       // 49152
#define NSTAGE 4
#define DYN_SMEM (NSTAGE*STG + 1024)   // 197632

// ---------------- device scratch (static, allocation-free) ----------------
__device__ int    g_topk_idx[NPAIR];
__device__ float  g_topk_w[NPAIR];
__device__ int    g_counts[NEXP];
__device__ int    g_list[NEXP*T_TOK];
__device__ __half g_xbuf_h[(size_t)T_TOK*HID];          // fp16 hidden
__device__ __half g_hbuf_h[(size_t)(NPAIR+256)*IDIM];   // fp16 silu(g)*u
__device__ float  g_outbuf[(size_t)NPAIR*HID];

// ---------------- helpers ----------------
__device__ __forceinline__ uint32_t packh2(float a, float b) {
    __half2 h = __floats2half2_rn(a, b);
    return *(uint32_t*)&h;
}
__device__ __forceinline__ void mma_f16(float* c, uint32_t a0, uint32_t a1, uint32_t a2, uint32_t a3,
                                        uint32_t b0, uint32_t b1) {
    asm volatile(
        "mma.sync.aligned.m16n8k16.row.col.f32.f16.f16.f32 "
        "{%0,%1,%2,%3}, {%4,%5,%6,%7}, {%8,%9}, {%0,%1,%2,%3};\n"
        : "+f"(c[0]), "+f"(c[1]), "+f"(c[2]), "+f"(c[3])
        : "r"(a0), "r"(a1), "r"(a2), "r"(a3), "r"(b0), "r"(b1));
}
__device__ __forceinline__ void cp_async16(uint32_t smem_addr, const void* gptr) {
    asm volatile("cp.async.cg.shared.global [%0], [%1], 16;\n"
                 :: "r"(smem_addr), "l"(gptr));
}
__device__ __forceinline__ void cp_commit() { asm volatile("cp.async.commit_group;\n"); }
template<int N> __device__ __forceinline__ void cp_wait() {
    asm volatile("cp.async.wait_group %0;\n" :: "n"(N));
}

// ---------------- 1. router (+ fused fp16 conversion of hidden) ------------
__global__ void router_kernel(const float* __restrict__ x, const float* __restrict__ gw) {
    __shared__ float Xs[16][68];
    __shared__ float Gs[64][68];
    __shared__ float Ls[16][64];
    const int tid = threadIdx.x;
    const int t0  = blockIdx.x * 16;
    const int tl  = tid & 15;
    const int eg  = tid >> 4;

    float acc[4] = {0.f, 0.f, 0.f, 0.f};

    for (int kk = 0; kk < HID; kk += 64) {
        {
            int r = tid >> 4, c = (tid & 15) * 4;
            float4 v = *(const float4*)(x + (size_t)(t0 + r) * HID + kk + c);
            Xs[r][c] = v.x; Xs[r][c+1] = v.y; Xs[r][c+2] = v.z; Xs[r][c+3] = v.w;
            uint2 hv;
            hv.x = packh2(v.x, v.y);
            hv.y = packh2(v.z, v.w);
            *(uint2*)(g_xbuf_h + (size_t)(t0 + r) * HID + kk + c) = hv;
        }
        #pragma unroll
        for (int i = 0; i < 4; i++) {
            int idx = i * 256 + tid;
            int r = idx >> 4, c = (idx & 15) * 4;
            float4 v = *(const float4*)(gw + (size_t)r * HID + kk + c);
            Gs[r][c] = v.x; Gs[r][c+1] = v.y; Gs[r][c+2] = v.z; Gs[r][c+3] = v.w;
        }
        __syncthreads();
        #pragma unroll 4
        for (int k = 0; k < 64; k += 4) {
            float4 xv = *(const float4*)&Xs[tl][k];
            #pragma unroll
            for (int j = 0; j < 4; j++) {
                float4 gv = *(const float4*)&Gs[eg*4 + j][k];
                acc[j] += xv.x*gv.x + xv.y*gv.y + xv.z*gv.z + xv.w*gv.w;
            }
        }
        __syncthreads();
    }
    #pragma unroll
    for (int j = 0; j < 4; j++) Ls[tl][eg*4 + j] = acc[j];
    __syncthreads();

    const int wid = tid >> 5, lane = tid & 31;
    for (int j = 0; j < 2; j++) {
        const int tok = wid * 2 + j;
        float v0 = Ls[tok][lane];
        float v1 = Ls[tok][lane + 32];
        bool s0 = false, s1 = false;
        float vals[8]; int idxs[8];
        #pragma unroll
        for (int r = 0; r < 8; r++) {
            float bv = -1e30f; int bi = 1 << 20;
            if (!s0) { bv = v0; bi = lane; }
            if (!s1 && (v1 > bv || (v1 == bv && lane + 32 < bi))) { bv = v1; bi = lane + 32; }
            #pragma unroll
            for (int o = 16; o > 0; o >>= 1) {
                float ov = __shfl_xor_sync(0xffffffffu, bv, o);
                int   oi = __shfl_xor_sync(0xffffffffu, bi, o);
                if (ov > bv || (ov == bv && oi < bi)) { bv = ov; bi = oi; }
            }
            vals[r] = bv; idxs[r] = bi;
            if (bi == lane)      s0 = true;
            if (bi == lane + 32) s1 = true;
        }
        if (lane == 0) {
            float m = vals[0];
            float w[8]; float sum = 0.f;
            #pragma unroll
            for (int r = 0; r < 8; r++) { w[r] = __expf(vals[r] - m); sum += w[r]; }
            float inv = 1.f / sum;
            int gt = t0 + tok;
            #pragma unroll
            for (int r = 0; r < 8; r++) {
                g_topk_idx[gt*TOPK + r] = idxs[r];
                g_topk_w  [gt*TOPK + r] = w[r] * inv;
            }
        }
    }
}

// ---------------- 2. bucketing ----------------
__global__ void bucket_kernel() {
    const int e = blockIdx.x;
    const int tid = threadIdx.x;
    __shared__ int warp_tot[8];
    __shared__ int base_s;
    if (tid == 0) base_s = 0;
    __syncthreads();
    const int wid = tid >> 5, lane = tid & 31;
    for (int t0 = 0; t0 < T_TOK; t0 += 256) {
        int t = t0 + tid;
        int slot = -1;
        #pragma unroll
        for (int k = 0; k < TOPK; k++)
            if (g_topk_idx[t*TOPK + k] == e) slot = k;
        unsigned m = __ballot_sync(0xffffffffu, slot >= 0);
        if (lane == 0) warp_tot[wid] = __popc(m);
        __syncthreads();
        int wbase = base_s;
        for (int i = 0; i < wid; i++) wbase += warp_tot[i];
        if (slot >= 0) {
            int pos = wbase + __popc(m & ((1u << lane) - 1u));
            g_list[e*T_TOK + pos] = t*TOPK + slot;
        }
        __syncthreads();
        if (tid == 0) {
            int tot = 0;
            for (int i = 0; i < 8; i++) tot += warp_tot[i];
            base_s += tot;
        }
        __syncthreads();
    }
    if (tid == 0) g_counts[e] = base_s;
}

// =====================================================================
// BM=256 tiles, 512 threads (16 warps, 4m x 4n), 1 CTA/SM, 4-stage pipe.
// Stage: A 256 rows x 128B (swizzled) then B 128 rows x 128B.
// 16B chunk c of row r at r*128 + ((c ^ (r&7))*16). BK=64 halfs.
// A via cp.async depth-3 prefetch; B via LDG(+2)->regs->STS(+1).
// =====================================================================

// ---------------- 3. GEMM1: h = silu(X Wg^T) * (X Wu^T) ----------------
__global__ void __launch_bounds__(512, 1)
gemm_gateup(const float* __restrict__ wg,
            const float* __restrict__ wu) {
    const int mb = blockIdx.x, nb = blockIdx.y, e = blockIdx.z;
    const int cnt = g_counts[e];
    if (mb * 256 >= cnt) return;

    extern __shared__ char smraw[];
    uint32_t sm0 = (uint32_t)__cvta_generic_to_shared(smraw);
    uint32_t smA = (sm0 + 1023u) & ~1023u;
    char*    smg = smraw + (smA - sm0);

    __shared__ int toks_s[256];
    __shared__ int cnt_s[NEXP];

    const int tid = threadIdx.x;
    if (tid < NEXP) cnt_s[tid] = g_counts[tid];
    if (tid < 256) {
        int m = mb * 256 + tid;
        toks_s[tid] = (m < cnt) ? (g_list[e*T_TOK + m] >> 3) : -1;
    }
    __syncthreads();
    int base = 0;
    for (int i = 0; i < e; i++) base += cnt_s[i];

    const int rows = min(cnt - mb * 256, 256);

    const int n0 = nb * 64;
    const float* wg_p = wg + ((size_t)e * IDIM + n0) * HID;
    const float* wu_p = wu + ((size_t)e * IDIM + n0) * HID;

    // A: 2048 chunks / 512 thr = 4 per thread; padded rows skipped
    auto cpA = [&](int kt, int s) {
        const int kk = kt * 64;
        const uint32_t st = smA + (uint32_t)(s * STG);
        #pragma unroll
        for (int it = 0; it < 4; it++) {
            int fid = it * 512 + tid;
            int r = fid >> 3, c = fid & 7;
            int tok = toks_s[r];
            if (tok >= 0)
                cp_async16(st + (uint32_t)(r * 128 + ((c ^ (r & 7)) * 16)),
                           g_xbuf_h + (size_t)tok * HID + kk + c * 8);
        }
    };
    // B: 1024 chunks / 512 thr = 2 per thread
    uint32_t rBh[8];
    auto ldgB = [&](int kt) {
        const int kk = kt * 64;
        #pragma unroll
        for (int it = 0; it < 2; it++) {
            int fid = it * 512 + tid;
            int r = fid >> 3, c = fid & 7;
            const float* src = (r < 64) ? wg_p + (size_t)r * HID + kk + c * 8
                                        : wu_p + (size_t)(r - 64) * HID + kk + c * 8;
            float4 v0 = *(const float4*)src;
            float4 v1 = *(const float4*)(src + 4);
            rBh[it*4+0] = packh2(v0.x, v0.y);
            rBh[it*4+1] = packh2(v0.z, v0.w);
            rBh[it*4+2] = packh2(v1.x, v1.y);
            rBh[it*4+3] = packh2(v1.z, v1.w);
        }
    };
    auto stsB = [&](int s) {
        #pragma unroll
        for (int it = 0; it < 2; it++) {
            int fid = it * 512 + tid;
            int r = fid >> 3, c = fid & 7;
            *(uint4*)(smg + s * STG + STG_A + r * 128 + ((c ^ (r & 7)) * 16))
                = make_uint4(rBh[it*4+0], rBh[it*4+1], rBh[it*4+2], rBh[it*4+3]);
        }
    };

    float cg[4][2][4], cu[4][2][4];
    #pragma unroll
    for (int a = 0; a < 4; a++)
        #pragma unroll
        for (int b = 0; b < 2; b++)
            #pragma unroll
            for (int c = 0; c < 4; c++) { cg[a][b][c] = 0.f; cu[a][b][c] = 0.f; }

    const int wid = tid >> 5, lane = tid & 31;
    const int wm = wid & 3, wn = wid >> 2;        // 4m x 4n
    const int grp = lane >> 2, tg = lane & 3;

    const int rows_w = max(0, min(rows - wm * 64, 64));
    const int mtmax  = (rows_w + 15) >> 4;
    const bool full  = (rows_w == 64);

    const int KT = HID / 64;                       // 32
    ldgB(0);
    cpA(0, 0); cp_commit();
    stsB(0);
    cpA(1, 1); cp_commit();
    cpA(2, 2); cp_commit();
    ldgB(1);

    for (int kt = 0; kt < KT; kt++) {
        cp_wait<2>();
        __syncthreads();                           // stage kt (A + B) ready; compute(kt-1) done
        if (kt + 1 < KT) stsB((kt + 1) & 3);
        if (kt + 3 < KT) cpA(kt + 3, (kt + 3) & 3);
        cp_commit();
        if (kt + 2 < KT) ldgB(kt + 2);

        const char* st = smg + (kt & 3) * STG;
        if (full) {
            #pragma unroll
            for (int p = 0; p < 2; p++) {
                const int cA = ((2 * tg + p) ^ grp) * 16;
                uint4 Bg[2], Bu[2];
                #pragma unroll
                for (int nf = 0; nf < 2; nf++) {
                    int br = wn * 16 + nf * 8 + grp;
                    Bg[nf] = *(const uint4*)(st + STG_A + br * 128 + cA);
                    Bu[nf] = *(const uint4*)(st + STG_A + (br + 64) * 128 + cA);
                }
                #pragma unroll
                for (int mt = 0; mt < 4; mt++) {
                    int ar = wm * 64 + mt * 16 + grp;
                    uint4 Alo = *(const uint4*)(st + ar * 128 + cA);
                    uint4 Ahi = *(const uint4*)(st + (ar + 8) * 128 + cA);
                    #pragma unroll
                    for (int nf = 0; nf < 2; nf++) {
                        mma_f16(cg[mt][nf], Alo.x, Ahi.x, Alo.y, Ahi.y, Bg[nf].x, Bg[nf].y);
                        mma_f16(cu[mt][nf], Alo.x, Ahi.x, Alo.y, Ahi.y, Bu[nf].x, Bu[nf].y);
                    }
                    #pragma unroll
                    for (int nf = 0; nf < 2; nf++) {
                        mma_f16(cg[mt][nf], Alo.z, Ahi.z, Alo.w, Ahi.w, Bg[nf].z, Bg[nf].w);
                        mma_f16(cu[mt][nf], Alo.z, Ahi.z, Alo.w, Ahi.w, Bu[nf].z, Bu[nf].w);
                    }
                }
            }
        } else if (mtmax > 0) {
            #pragma unroll
            for (int p = 0; p < 2; p++) {
                const int cA = ((2 * tg + p) ^ grp) * 16;
                uint4 Bg[2], Bu[2];
                #pragma unroll
                for (int nf = 0; nf < 2; nf++) {
                    int br = wn * 16 + nf * 8 + grp;
                    Bg[nf] = *(const uint4*)(st + STG_A + br * 128 + cA);
                    Bu[nf] = *(const uint4*)(st + STG_A + (br + 64) * 128 + cA);
                }
                #pragma unroll
                for (int mt = 0; mt < 4; mt++) {
                    if (mt < mtmax) {
                        int ar = wm * 64 + mt * 16 + grp;
                        uint4 Alo = *(const uint4*)(st + ar * 128 + cA);
                        uint4 Ahi = *(const uint4*)(st + (ar + 8) * 128 + cA);
                        #pragma unroll
                        for (int nf = 0; nf < 2; nf++) {
                            mma_f16(cg[mt][nf], Alo.x, Ahi.x, Alo.y, Ahi.y, Bg[nf].x, Bg[nf].y);
                            mma_f16(cu[mt][nf], Alo.x, Ahi.x, Alo.y, Ahi.y, Bu[nf].x, Bu[nf].y);
                        }
                        #pragma unroll
                        for (int nf = 0; nf < 2; nf++) {
                            mma_f16(cg[mt][nf], Alo.z, Ahi.z, Alo.w, Ahi.w, Bg[nf].z, Bg[nf].w);
                            mma_f16(cu[mt][nf], Alo.z, Ahi.z, Alo.w, Ahi.w, Bu[nf].z, Bu[nf].w);
                        }
                    }
                }
            }
        }
    }

    // ---- epilogue: silu(g)*u -> fp16 g_hbuf_h ----
    #pragma unroll
    for (int mt = 0; mt < 4; mt++) {
        #pragma unroll
        for (int hl = 0; hl < 2; hl++) {
            int row = wm * 64 + mt * 16 + hl * 8 + grp;
            int m = mb * 256 + row;
            if (m < cnt) {
                __half* hrow = g_hbuf_h + (size_t)(base + m) * IDIM + n0;
                #pragma unroll
                for (int nf = 0; nf < 2; nf++) {
                    int col = wn * 16 + nf * 8 + tg * 2;
                    float g0 = cg[mt][nf][hl*2 + 0], u0 = cu[mt][nf][hl*2 + 0];
                    float g1 = cg[mt][nf][hl*2 + 1], u1 = cu[mt][nf][hl*2 + 1];
                    float h0 = g0 * u0 / (1.f + __expf(-g0));
                    float h1 = g1 * u1 / (1.f + __expf(-g1));
                    *(uint32_t*)(hrow + col) = packh2(h0, h1);
                }
            }
        }
    }
}

// ---------------- 4. GEMM2: y = (h Wd^T) * combine_w -> g_outbuf ----------
__global__ void __launch_bounds__(512, 1)
gemm_down(const float* __restrict__ wd) {
    const int mb = blockIdx.x, nb = blockIdx.y, e = blockIdx.z;
    const int cnt = g_counts[e];
    if (mb * 256 >= cnt) return;

    extern __shared__ char smraw[];
    uint32_t sm0 = (uint32_t)__cvta_generic_to_shared(smraw);
    uint32_t smA = (sm0 + 1023u) & ~1023u;
    char*    smg = smraw + (smA - sm0);

    __shared__ int pairs_s[256];
    __shared__ int cnt_s[NEXP];

    const int tid = threadIdx.x;
    if (tid < NEXP) cnt_s[tid] = g_counts[tid];
    if (tid < 256) {
        int m = mb * 256 + tid;
        pairs_s[tid] = (m < cnt) ? g_list[e*T_TOK + m] : -1;
    }
    __syncthreads();
    int base = 0;
    for (int i = 0; i < e; i++) base += cnt_s[i];

    const int rows = min(cnt - mb * 256, 256);

    const int n0 = nb * 128;
    const float*  wd_p  = wd + ((size_t)e * HID + n0) * IDIM;
    const __half* arow0 = g_hbuf_h + (size_t)(base + mb * 256) * IDIM;

    auto cpA = [&](int kt, int s) {
        const int kk = kt * 64;
        const uint32_t st = smA + (uint32_t)(s * STG);
        #pragma unroll
        for (int it = 0; it < 4; it++) {
            int fid = it * 512 + tid;
            int r = fid >> 3, c = fid & 7;
            if (pairs_s[r] >= 0)
                cp_async16(st + (uint32_t)(r * 128 + ((c ^ (r & 7)) * 16)),
                           arow0 + (size_t)r * IDIM + kk + c * 8);
        }
    };
    uint32_t rBh[8];
    auto ldgB = [&](int kt) {
        const int kk = kt * 64;
        #pragma unroll
        for (int it = 0; it < 2; it++) {
            int fid = it * 512 + tid;
            int r = fid >> 3, c = fid & 7;
            const float* src = wd_p + (size_t)r * IDIM + kk + c * 8;
            float4 v0 = *(const float4*)src;
            float4 v1 = *(const float4*)(src + 4);
            rBh[it*4+0] = packh2(v0.x, v0.y);
            rBh[it*4+1] = packh2(v0.z, v0.w);
            rBh[it*4+2] = packh2(v1.x, v1.y);
            rBh[it*4+3] = packh2(v1.z, v1.w);
        }
    };
    auto stsB = [&](int s) {
        #pragma unroll
        for (int it = 0; it < 2; it++) {
            int fid = it * 512 + tid;
            int r = fid >> 3, c = fid & 7;
            *(uint4*)(smg + s * STG + STG_A + r * 128 + ((c ^ (r & 7)) * 16))
                = make_uint4(rBh[it*4+0], rBh[it*4+1], rBh[it*4+2], rBh[it*4+3]);
        }
    };

    float cd[4][4][4];
    #pragma unroll
    for (int a = 0; a < 4; a++)
        #pragma unroll
        for (int b = 0; b < 4; b++)
            #pragma unroll
            for (int c = 0; c < 4; c++) cd[a][b][c] = 0.f;

    const int wid = tid >> 5, lane = tid & 31;
    const int wm = wid & 3, wn = wid >> 2;
    const int grp = lane >> 2, tg = lane & 3;

    const int rows_w = max(0, min(rows - wm * 64, 64));
    const int mtmax  = (rows_w + 15) >> 4;
    const bool full  = (rows_w == 64);

    const int KT = IDIM / 64;                      // 12
    ldgB(0);
    cpA(0, 0); cp_commit();
    stsB(0);
    cpA(1, 1); cp_commit();
    cpA(2, 2); cp_commit();
    ldgB(1);

    for (int kt = 0; kt < KT; kt++) {
        cp_wait<2>();
        __syncthreads();
        if (kt + 1 < KT) stsB((kt + 1) & 3);
        if (kt + 3 < KT) cpA(kt + 3, (kt + 3) & 3);
        cp_commit();
        if (kt + 2 < KT) ldgB(kt + 2);

        const char* st = smg + (kt & 3) * STG;
        if (full) {
            #pragma unroll
            for (int p = 0; p < 2; p++) {
                const int cA = ((2 * tg + p) ^ grp) * 16;
                uint4 Bw[4];
                #pragma unroll
                for (int nf = 0; nf < 4; nf++) {
                    int br = wn * 32 + nf * 8 + grp;
                    Bw[nf] = *(const uint4*)(st + STG_A + br * 128 + cA);
                }
                #pragma unroll
                for (int mt = 0; mt < 4; mt++) {
                    int ar = wm * 64 + mt * 16 + grp;
                    uint4 Alo = *(const uint4*)(st + ar * 128 + cA);
                    uint4 Ahi = *(const uint4*)(st + (ar + 8) * 128 + cA);
                    #pragma unroll
                    for (int nf = 0; nf < 4; nf++)
                        mma_f16(cd[mt][nf], Alo.x, Ahi.x, Alo.y, Ahi.y, Bw[nf].x, Bw[nf].y);
                    #pragma unroll
                    for (int nf = 0; nf < 4; nf++)
                        mma_f16(cd[mt][nf], Alo.z, Ahi.z, Alo.w, Ahi.w, Bw[nf].z, Bw[nf].w);
                }
            }
        } else if (mtmax > 0) {
            #pragma unroll
            for (int p = 0; p < 2; p++) {
                const int cA = ((2 * tg + p) ^ grp) * 16;
                uint4 Bw[4];
                #pragma unroll
                for (int nf = 0; nf < 4; nf++) {
                    int br = wn * 32 + nf * 8 + grp;
                    Bw[nf] = *(const uint4*)(st + STG_A + br * 128 + cA);
                }
                #pragma unroll
                for (int mt = 0; mt < 4; mt++) {
                    if (mt < mtmax) {
                        int ar = wm * 64 + mt * 16 + grp;
                        uint4 Alo = *(const uint4*)(st + ar * 128 + cA);
                        uint4 Ahi = *(const uint4*)(st + (ar + 8) * 128 + cA);
                        #pragma unroll
                        for (int nf = 0; nf < 4; nf++)
                            mma_f16(cd[mt][nf], Alo.x, Ahi.x, Alo.y, Ahi.y, Bw[nf].x, Bw[nf].y);
                        #pragma unroll
                        for (int nf = 0; nf < 4; nf++)
                            mma_f16(cd[mt][nf], Alo.z, Ahi.z, Alo.w, Ahi.w, Bw[nf].z, Bw[nf].w);
                    }
                }
            }
        }
    }

    // ---- epilogue: scale by combine weight, streaming-store per-pair row ----
    #pragma unroll
    for (int mt = 0; mt < 4; mt++) {
        #pragma unroll
        for (int hl = 0; hl < 2; hl++) {
            int row = wm * 64 + mt * 16 + hl * 8 + grp;
            int pair = pairs_s[row];
            if (pair >= 0) {
                float w = g_topk_w[pair];
                float* orow = g_outbuf + (size_t)pair * HID + n0;
                #pragma unroll
                for (int nf = 0; nf < 4; nf++) {
                    int col = wn * 32 + nf * 8 + tg * 2;
                    float2 ov;
                    ov.x = cd[mt][nf][hl*2 + 0] * w;
                    ov.y = cd[mt][nf][hl*2 + 1] * w;
                    __stcs((float2*)(orow + col), ov);
                }
            }
        }
    }
}

// ---------------- 5. final reduce ----------------
__global__ void reduce_kernel(float* __restrict__ out) {
    int idx = blockIdx.x * blockDim.x + threadIdx.x;
    int t = idx >> 9;
    int h4 = idx & 511;
    const float4* ob = (const float4*)g_outbuf;
    float4 s = __ldcs(&ob[(size_t)(t * TOPK) * (HID/4) + h4]);
    #pragma unroll
    for (int k = 1; k < TOPK; k++) {
        float4 v = __ldcs(&ob[(size_t)(t * TOPK + k) * (HID/4) + h4]);
        s.x += v.x; s.y += v.y; s.z += v.z; s.w += v.w;
    }
    ((float4*)out)[idx] = s;
}

// ---------------- launch ----------------
extern "C" void kernel_launch(void* const* d_in, const int* in_sizes, int n_in,
                              void* d_out, int out_size) {
    (void)in_sizes; (void)n_in; (void)out_size;
    const float* hidden = (const float*)d_in[0];
    const float* gate_w = (const float*)d_in[1];
    const float* w_gate = (const float*)d_in[2];
    const float* w_up   = (const float*)d_in[3];
    const float* w_down = (const float*)d_in[4];
    float* out = (float*)d_out;

    cudaFuncSetAttribute(gemm_gateup, cudaFuncAttributeMaxDynamicSharedMemorySize, DYN_SMEM);
    cudaFuncSetAttribute(gemm_down,   cudaFuncAttributeMaxDynamicSharedMemorySize, DYN_SMEM);

    router_kernel<<<T_TOK/16, 256>>>(hidden, gate_w);                 // idx 0
    bucket_kernel<<<NEXP, 256>>>();                                   // idx 1
    gemm_gateup<<<dim3(T_TOK/256, IDIM/64, NEXP), 512, DYN_SMEM>>>(w_gate, w_up);  // idx 2
    gemm_down  <<<dim3(T_TOK/256, HID/128, NEXP), 512, DYN_SMEM>>>(w_down);        // idx 3
    reduce_kernel<<<(T_TOK*(HID/4))/256, 256>>>(out);
}